// round 4
// baseline (speedup 1.0000x reference)
#include <cuda_runtime.h>

#define HH   512
#define WW   512
#define BB   4
#define CINC 55
#define NRr  30
#define NCc  20
#define NCELL 600
#define OUTX 57671680   // 4*55*512*512

typedef unsigned long long u64;

// Scratch (device globals; no allocation)
__device__ float g_Stop[NCELL];
__device__ float g_Sbot[NCELL];
__device__ float g_topm[NCELL];
__device__ float g_sig[NCELL];
__device__ float g_wtsum[18];
__device__ float g_btsum;
// duplicated weight pairs: [c][d][o][k], each entry = (w, w) packed in 64 bits
__device__ u64  g_wpack[CINC * 450];

__device__ __forceinline__ u64 ffma2(u64 a, u64 b, u64 c) {
    u64 d;
    asm("fma.rn.f32x2 %0, %1, %2, %3;" : "=l"(d) : "l"(a), "l"(b), "l"(c));
    return d;
}
__device__ __forceinline__ float2 unpack2(u64 v) {
    float2 f;
    asm("mov.b64 {%0, %1}, %2;" : "=f"(f.x), "=f"(f.y) : "l"(v));
    return f;
}

// ---------------------------------------------------------------------------
// Kernel 1: zero accumulators, fold top head (36ch -> channel-sum 18-vector),
// and pre-pack duplicated conv-weight pairs into g_wpack for __ldg access.
// ---------------------------------------------------------------------------
__global__ __launch_bounds__(640) void prep_kernel(
    const float* __restrict__ w1, const float* __restrict__ w2,
    const float* __restrict__ w3,
    const float* __restrict__ wt, const float* __restrict__ bt)
{
    int t = blockIdx.x * blockDim.x + threadIdx.x;
    const int total = 3 * 6 * CINC * 25;   // 24750
    if (t < total) {
        int d  = t / (6 * CINC * 25);
        int r  = t - d * (6 * CINC * 25);
        int o  = r / (CINC * 25);
        int r2 = r - o * (CINC * 25);
        int c  = r2 / 25;
        int k  = r2 - c * 25;
        const float* w = (d == 0) ? w1 : (d == 1 ? w2 : w3);
        unsigned bits = __float_as_uint(w[(o * CINC + c) * 25 + k]);
        g_wpack[c * 450 + d * 150 + o * 25 + k] = ((u64)bits << 32) | (u64)bits;
    }
    if (blockIdx.x == 0) {
        int s = threadIdx.x;
        if (s < NCELL) { g_Stop[s] = 0.f; g_Sbot[s] = 0.f; }
        if (s < 18) {
            float a = 0.f;
            #pragma unroll 4
            for (int c = 0; c < 36; c++) a += wt[c * 18 + s];
            g_wtsum[s] = a;
        }
        if (s == 18) {
            float a = 0.f;
            for (int c = 0; c < 36; c++) a += bt[c];
            g_btsum = a;
        }
    }
}

// ---------------------------------------------------------------------------
// Kernel 2: fused 3x dilated 5x5 conv (55->18) + ReLU + feat store +
//           per-cell head accumulation. FFMA2 (f32x2) x-pair packing:
//           each thread computes 2 adjacent x-pixels per packed FMA.
// Tile: 32x32 outputs, 128 threads (16 x-pairs x 8 rows), 4 row-groups/thread.
// Two tile copies (tB shifted by one float) keep every pair load an aligned
// LDS.64; weights arrive as pre-duplicated pairs via __ldg (no crossbar).
// ---------------------------------------------------------------------------
__global__ __launch_bounds__(128, 2) void conv_kernel(
    const float* __restrict__ x,
    const int*   __restrict__ row_seg,
    const int*   __restrict__ col_seg,
    const float* __restrict__ b1, const float* __restrict__ b2,
    const float* __restrict__ b3,
    const float* __restrict__ wbv, const float* __restrict__ bbv,
    float* __restrict__ out)
{
    __shared__ __align__(16) float tA[44 * 44];
    __shared__ __align__(16) float tB[44 * 44];   // tB[j] = tA[j+1] per row
    __shared__ float sbias[18], swt[18], swb[18];
    __shared__ float sbt, sbb;
    __shared__ float cT[NCELL], cB[NCELL];

    const int tid = threadIdx.x;
    const int tx  = tid & 15;      // x-pair index
    const int ty  = tid >> 4;      // row within 8-row group
    const int gx0 = blockIdx.x * 32;
    const int gy0 = blockIdx.y * 32;
    const int b   = blockIdx.z;

    for (int t = tid; t < NCELL; t += 128) { cT[t] = 0.f; cB[t] = 0.f; }
    if (tid < 6) {
        sbias[tid]      = b1[tid];
        sbias[6 + tid]  = b2[tid];
        sbias[12 + tid] = b3[tid];
    }
    if (tid < 18) { swt[tid] = g_wtsum[tid]; swb[tid] = wbv[tid]; }
    if (tid == 0) { sbt = g_btsum; sbb = bbv[0]; }

    u64 acc[4][18];
    #pragma unroll
    for (int p = 0; p < 4; p++) {
        #pragma unroll
        for (int j = 0; j < 18; j++) acc[p][j] = 0ull;
    }

    for (int c = 0; c < CINC; c++) {
        const float* xc = x + (((size_t)(b * CINC + c)) << 18);
        for (int t = tid; t < 44 * 44; t += 128) {
            int rr = t / 44, cc = t - rr * 44;
            int gy = gy0 - 6 + rr;
            int gx = gx0 - 6 + cc;
            float v = 0.f;
            if ((unsigned)gy < 512u && (unsigned)gx < 512u)
                v = xc[(gy << 9) + gx];
            tA[t] = v;
            if (cc > 0) tB[t - 1] = v;
        }
        __syncthreads();

        const u64* wc = g_wpack + c * 450;
        #pragma unroll
        for (int ky = 0; ky < 5; ky++) {
            #pragma unroll
            for (int kx = 0; kx < 5; kx++) {
                const int k = ky * 5 + kx;
                u64 w[18];
                #pragma unroll
                for (int o = 0; o < 6; o++) {
                    w[o]      = __ldg(wc +       o * 25 + k);
                    w[6 + o]  = __ldg(wc + 150 + o * 25 + k);
                    w[12 + o] = __ldg(wc + 300 + o * 25 + k);
                }
                #pragma unroll
                for (int p = 0; p < 4; p++) {
                    const int yb = ty + 8 * p + 6;
                    const int xb = 2 * tx + 6;
                    // dilation 1 (odd col offsets use shifted copy tB)
                    {
                        const int r  = yb + (ky - 2);
                        const int cx = xb + (kx - 2);
                        u64 s = ((kx - 2) & 1)
                              ? *(const u64*)&tB[r * 44 + cx - 1]
                              : *(const u64*)&tA[r * 44 + cx];
                        #pragma unroll
                        for (int o = 0; o < 6; o++)
                            acc[p][o] = ffma2(s, w[o], acc[p][o]);
                    }
                    // dilation 2 (offsets always even -> tA)
                    {
                        const int r  = yb + 2 * (ky - 2);
                        const int cx = xb + 2 * (kx - 2);
                        u64 s = *(const u64*)&tA[r * 44 + cx];
                        #pragma unroll
                        for (int o = 0; o < 6; o++)
                            acc[p][6 + o] = ffma2(s, w[6 + o], acc[p][6 + o]);
                    }
                    // dilation 3
                    {
                        const int r  = yb + 3 * (ky - 2);
                        const int cx = xb + 3 * (kx - 2);
                        u64 s = ((3 * (kx - 2)) & 1)
                              ? *(const u64*)&tB[r * 44 + cx - 1]
                              : *(const u64*)&tA[r * 44 + cx];
                        #pragma unroll
                        for (int o = 0; o < 6; o++)
                            acc[p][12 + o] = ffma2(s, w[12 + o], acc[p][12 + o]);
                    }
                }
            }
        }
        __syncthreads();
    }

    // epilogue: bias+relu, float2 feat stores (channels 36..53), cell accum
    const int gx  = gx0 + 2 * tx;
    const int cs0 = col_seg[gx];
    const int cs1 = col_seg[gx + 1];
    #pragma unroll
    for (int p = 0; p < 4; p++) {
        const int gy    = gy0 + ty + 8 * p;
        const int cellb = row_seg[gy] * NCc;
        float st0 = sbt, st1 = sbt, sb0 = sbb, sb1 = sbb;
        const unsigned pix = ((unsigned)gy << 9) + (unsigned)gx;
        #pragma unroll
        for (int j = 0; j < 18; j++) {
            float2 v = unpack2(acc[p][j]);
            float f0 = fmaxf(v.x + sbias[j], 0.f);
            float f1 = fmaxf(v.y + sbias[j], 0.f);
            *(float2*)&out[(((unsigned)(b * CINC + 36 + j)) << 18) + pix] =
                make_float2(f0, f1);
            st0 = fmaf(swt[j], f0, st0);
            st1 = fmaf(swt[j], f1, st1);
            sb0 = fmaf(swb[j], f0, sb0);
            sb1 = fmaf(swb[j], f1, sb1);
        }
        atomicAdd(&cT[cellb + cs0], st0);
        atomicAdd(&cT[cellb + cs1], st1);
        atomicAdd(&cB[cellb + cs0], sb0);
        atomicAdd(&cB[cellb + cs1], sb1);
    }
    __syncthreads();
    for (int t = tid; t < NCELL; t += 128) {
        float v0 = cT[t], v1 = cB[t];
        if (v0 != 0.f) atomicAdd(&g_Stop[t], v0);
        if (v1 != 0.f) atomicAdd(&g_Sbot[t], v1);
    }
}

// ---------------------------------------------------------------------------
// Kernel 3: finalize means -> top_m, sigmoid(bot_m); write pools output.
// ---------------------------------------------------------------------------
__global__ __launch_bounds__(640) void finalize_kernel(
    const int* __restrict__ row_seg, const int* __restrict__ col_seg,
    float* __restrict__ out)
{
    __shared__ int rc[NRr];
    __shared__ int cc[NCc];
    int t = threadIdx.x;
    if (t < NRr) rc[t] = 0;
    if (t < NCc) cc[t] = 0;
    __syncthreads();
    if (t < 512) {
        atomicAdd(&rc[row_seg[t]], 1);
        atomicAdd(&cc[col_seg[t]], 1);
    }
    __syncthreads();
    if (t < NCELL) {
        int r = t / NCc, c = t - r * NCc;
        float pix = (float)(rc[r] * cc[c]);
        float tm = g_Stop[t] / (pix * (float)(BB * 36));
        float bm = g_Sbot[t] / (pix * (float)BB);
        g_topm[t] = tm;
        float sg = 1.f / (1.f + expf(-bm));
        g_sig[t] = sg;
        #pragma unroll
        for (int b = 0; b < BB; b++)
            out[OUTX + b * NCELL + t] = sg;
    }
}

// ---------------------------------------------------------------------------
// Kernel 4: broadcast fill of channels 0..35 (top_m) and 54 (sigmoid(bot_m)).
// float4 stores: 4 consecutive x per thread.
// ---------------------------------------------------------------------------
__global__ __launch_bounds__(256) void bcast_kernel(
    const int* __restrict__ row_seg, const int* __restrict__ col_seg,
    float* __restrict__ out)
{
    unsigned i  = blockIdx.x * 256u + threadIdx.x;   // over B*H*W/4
    unsigned x4 = (i & 127u) << 2;
    unsigned y  = (i >> 7) & 511u;
    unsigned b  = i >> 16;
    int rb = __ldg(&row_seg[y]) * NCc;
    int c0 = __ldg(&col_seg[x4]);
    int c1 = __ldg(&col_seg[x4 + 1]);
    int c2 = __ldg(&col_seg[x4 + 2]);
    int c3 = __ldg(&col_seg[x4 + 3]);
    float4 tv = make_float4(g_topm[rb + c0], g_topm[rb + c1],
                            g_topm[rb + c2], g_topm[rb + c3]);
    float4 sv = make_float4(g_sig[rb + c0], g_sig[rb + c1],
                            g_sig[rb + c2], g_sig[rb + c3]);
    unsigned base = ((b * (unsigned)CINC) << 18) + (y << 9) + x4;
    #pragma unroll
    for (int ch = 0; ch < 36; ch++)
        *(float4*)&out[base + ((unsigned)ch << 18)] = tv;
    *(float4*)&out[base + (54u << 18)] = sv;
}

// ---------------------------------------------------------------------------
extern "C" void kernel_launch(void* const* d_in, const int* in_sizes, int n_in,
                              void* d_out, int out_size) {
    const float* x       = (const float*)d_in[0];
    const int*   row_seg = (const int*)d_in[1];
    const int*   col_seg = (const int*)d_in[2];
    const float* w1 = (const float*)d_in[3];
    const float* b1 = (const float*)d_in[4];
    const float* w2 = (const float*)d_in[5];
    const float* b2 = (const float*)d_in[6];
    const float* w3 = (const float*)d_in[7];
    const float* b3 = (const float*)d_in[8];
    const float* wt = (const float*)d_in[9];
    const float* bt = (const float*)d_in[10];
    const float* wb = (const float*)d_in[11];
    const float* bb = (const float*)d_in[12];
    float* out = (float*)d_out;

    prep_kernel<<<39, 640>>>(w1, w2, w3, wt, bt);

    dim3 grid(WW / 32, HH / 32, BB);
    conv_kernel<<<grid, 128>>>(x, row_seg, col_seg,
                               b1, b2, b3, wb, bb, out);

    finalize_kernel<<<1, 640>>>(row_seg, col_seg, out);

    bcast_kernel<<<(BB * HH * WW / 4) / 256, 256>>>(row_seg, col_seg, out);
}